// round 14
// baseline (speedup 1.0000x reference)
#include <cuda_runtime.h>
#include <math.h>
#include <stdint.h>

#define NPT 60000
#define EPSBN 1e-5f

typedef unsigned long long ull;

__device__ float g_coords[NPT * 3];
__device__ float g_q   [NPT * 128];
__device__ float g_qh  [NPT * 128];
__device__ float g_KV  [(size_t)NPT * 256];   // [n][Kf(128) | Vf(128)]
__device__ float g_att2[NPT * 128];
__device__ float g_x1  [NPT * 128];
__device__ float g_x1n [NPT * 128];
__device__ float g_ff1 [(size_t)NPT * 512];
__device__ float g_x2  [NPT * 128];
__device__ float g_x2n [NPT * 128];
__device__ float g_y   [NPT * 128];
__device__ float g_part[128 * 256];
__device__ float g_sums[256];

#define FFMA2(d, a, b) asm("fma.rn.f32x2 %0, %1, %2, %0;" : "+l"(d) : "l"(a), "l"(b))
#define PACKF(d, a, b) asm("mov.b64 %0, {%1, %2};" : "=l"(d) : "f"(a), "f"(b))
#define UNPKF(lo, hi, v) asm("mov.b64 {%0, %1}, %2;" : "=f"(lo), "=f"(hi) : "l"(v))

// ---- coords + q = features + relu(coords @ qpos_w.T + b) ----
__global__ void coords_q_kernel(const int* __restrict__ ind, const float* __restrict__ f,
                                const float* __restrict__ qpw, const float* __restrict__ qpb,
                                float* __restrict__ coords, float* __restrict__ q, int n) {
    int idx = blockIdx.x * 256 + threadIdx.x;
    int row = idx >> 7, c = idx & 127;
    if (row >= n) return;
    float cx = ((float)ind[row*4+3] + 0.5f) * 0.1f - 40.0f;
    float cy = ((float)ind[row*4+2] + 0.5f) * 0.1f - 40.0f;
    float cz = ((float)ind[row*4+1] + 0.5f) * 0.2f - 3.0f;
    if (c == 0) { coords[row*3+0]=cx; coords[row*3+1]=cy; coords[row*3+2]=cz; }
    float p = cx*qpw[c*3+0] + cy*qpw[c*3+1] + cz*qpw[c*3+2] + qpb[c];
    q[idx] = f[idx] + fmaxf(p, 0.0f);
}

// ---- GEMM (R7-proven scalar version): Y = [relu]( X @ W^T + bias [+ res] ) ----
__global__ void gemm_kernel(const float* __restrict__ X, const float* __restrict__ W,
                            const float* __restrict__ bias, float* __restrict__ Y,
                            const float* __restrict__ res, int doRelu,
                            int n, int cin, int cout) {
    extern __shared__ float sm[];
    float* Xs = sm;               // 64x128
    float* Ws = sm + 64 * 128;    // 128x129 transposed
    int row0 = blockIdx.x * 64, j0 = blockIdx.y * 128;
    int tid = threadIdx.x, tx = tid & 31, ty = tid >> 5;
    float acc[8][4];
#pragma unroll
    for (int r = 0; r < 8; r++) { acc[r][0]=acc[r][1]=acc[r][2]=acc[r][3]=0.f; }

    for (int c0 = 0; c0 < cin; c0 += 128) {
#pragma unroll
        for (int i = 0; i < 8; i++) {
            int l = tid + 256*i, r = l >> 5, c4 = l & 31;
            int row = row0 + r;
            float4 v = make_float4(0.f,0.f,0.f,0.f);
            if (row < n) v = *(const float4*)(X + (size_t)row*cin + c0 + (c4<<2));
            *(float4*)(Xs + r*128 + (c4<<2)) = v;
        }
#pragma unroll 8
        for (int i = 0; i < 64; i++) {
            int l = tid + 256*i, j = l >> 7, c = l & 127;
            Ws[c*129 + j] = W[(size_t)(j0+j)*cin + c0 + c];
        }
        __syncthreads();
#pragma unroll 2
        for (int c = 0; c < 128; ++c) {
            float w0 = Ws[c*129+tx],    w1 = Ws[c*129+tx+32];
            float w2 = Ws[c*129+tx+64], w3 = Ws[c*129+tx+96];
#pragma unroll
            for (int r = 0; r < 8; ++r) {
                float xv = Xs[(ty*8+r)*128 + c];
                acc[r][0]=fmaf(xv,w0,acc[r][0]); acc[r][1]=fmaf(xv,w1,acc[r][1]);
                acc[r][2]=fmaf(xv,w2,acc[r][2]); acc[r][3]=fmaf(xv,w3,acc[r][3]);
            }
        }
        __syncthreads();
    }
    float b0=bias[j0+tx], b1=bias[j0+tx+32], b2=bias[j0+tx+64], b3=bias[j0+tx+96];
#pragma unroll
    for (int r = 0; r < 8; ++r) {
        int row = row0 + ty*8 + r;
        if (row >= n) break;
        float v0=acc[r][0]+b0, v1=acc[r][1]+b1, v2=acc[r][2]+b2, v3=acc[r][3]+b3;
        size_t base = (size_t)row*cout + j0;
        if (res) { v0+=res[base+tx]; v1+=res[base+tx+32]; v2+=res[base+tx+64]; v3+=res[base+tx+96]; }
        if (doRelu) { v0=fmaxf(v0,0.f); v1=fmaxf(v1,0.f); v2=fmaxf(v2,0.f); v3=fmaxf(v3,0.f); }
        Y[base+tx]=v0; Y[base+tx+32]=v1; Y[base+tx+64]=v2; Y[base+tx+96]=v3;
    }
}

// ---- warp-per-query fused attention ----
// 384 threads = 12 warps; each warp handles 4 queries; lane = key (K=32).
// smem: wk[16384] | wvT[128*132] | kp[512] | per-warp{qh 128, qks 1280, attn 320}
#define AT_WARPS 12
#define AT_QPW 4
#define AT_QPB (AT_WARPS * AT_QPW)
#define AT_WARP_FLOATS (128 + 1280 + 320)
#define AT_SMEM_FLOATS (16384 + 128*132 + 512 + AT_WARPS*AT_WARP_FLOATS)

__global__ __launch_bounds__(384, 1) void attn_warp_kernel(
    const int* __restrict__ ki_g, const float* __restrict__ coords,
    const float* __restrict__ qh_g, const float* __restrict__ KV,
    const float* __restrict__ wk, const float* __restrict__ wv,
    const float* __restrict__ kpw, const float* __restrict__ kpb,
    float* __restrict__ att2, int n) {
    extern __shared__ float sm[];
    float* wk_s = sm;                        // [hd][c] 128x128
    float* wv_s = sm + 16384;                // [c'][c] pad 132
    float* kp_s = wv_s + 128*132;            // [c][4] = {w0,w1,w2,b}
    float* wbase = kp_s + 512;
    const int tid = threadIdx.x;
    const int w = tid >> 5, lane = tid & 31;
    float* qh_s = wbase + w * AT_WARP_FLOATS;    // 128
    float* qk_s = qh_s + 128;                    // [c][10] pairs (h)
    float* at_s = qk_s + 1280;                   // [k][10] pairs (h)

    for (int l = tid; l < 16384; l += 384) wk_s[l] = wk[l];
    for (int l = tid; l < 16384; l += 384) {
        int co = l >> 7, cp = l & 127;
        wv_s[cp*132 + co] = wv[l];
    }
    for (int c = tid; c < 128; c += 384) {
        kp_s[c*4+0] = kpw[c*3+0];
        kp_s[c*4+1] = kpw[c*3+1];
        kp_s[c*4+2] = kpw[c*3+2];
        kp_s[c*4+3] = kpb[c];
    }
    __syncthreads();

    const int cbase = lane << 2;       // this lane's 4 output channels
    const int hj    = lane >> 2;       // their head
    float4 kp[4];
#pragma unroll
    for (int i = 0; i < 4; i++) kp[i] = *(const float4*)(kp_s + (cbase+i)*4);

    for (int qi = 0; qi < AT_QPW; qi++) {
        int nq = blockIdx.x * AT_QPB + w * AT_QPW + qi;
        if (nq >= n) nq = n - 1;

        // phase 0: per-lane key meta + qh to smem
        int ki = ki_g[nq*32 + lane];
        int g  = ki < 0 ? 0 : ki;
        float qcx = coords[nq*3+0], qcy = coords[nq*3+1], qcz = coords[nq*3+2];
        float rx = coords[g*3+0] - qcx;
        float ry = coords[g*3+1] - qcy;
        float rz = coords[g*3+2] - qcz;
        *(float4*)(qh_s + cbase) = *(const float4*)(qh_g + (size_t)nq*128 + cbase);
        __syncwarp();

        // phase 1: qk[h][c] = sum_d qh[h*16+d]*wk[h*16+d][c], c in lane's 4 cols
        float acc[8][4];
#pragma unroll
        for (int h = 0; h < 8; h++) { acc[h][0]=acc[h][1]=acc[h][2]=acc[h][3]=0.f; }
#pragma unroll
        for (int h = 0; h < 8; h++)
#pragma unroll
            for (int d = 0; d < 16; d++) {
                float qv = qh_s[h*16+d];
                float4 w4 = *(const float4*)(wk_s + (h*16+d)*128 + cbase);
                acc[h][0]=fmaf(qv,w4.x,acc[h][0]); acc[h][1]=fmaf(qv,w4.y,acc[h][1]);
                acc[h][2]=fmaf(qv,w4.z,acc[h][2]); acc[h][3]=fmaf(qv,w4.w,acc[h][3]);
            }
#pragma unroll
        for (int i = 0; i < 4; i++)
#pragma unroll
            for (int m = 0; m < 4; m++) {
                ull p; PACKF(p, acc[2*m][i], acc[2*m+1][i]);
                *(ull*)(qk_s + (cbase+i)*10 + 2*m) = p;
            }
        __syncwarp();

        // phase 2: scores for this lane's key
        float a[8];
#pragma unroll
        for (int h = 0; h < 8; h++) a[h] = 0.f;
        const float4* kf4 = (const float4*)(KV + (size_t)g*256);
#pragma unroll
        for (int h = 0; h < 8; h++)
#pragma unroll
            for (int dq = 0; dq < 4; dq++) {
                float4 q4 = *(const float4*)(qh_s + h*16 + dq*4);
                float4 k4 = kf4[h*4 + dq];
                a[h] = fmaf(q4.x,k4.x, fmaf(q4.y,k4.y, fmaf(q4.z,k4.z,
                        fmaf(q4.w,k4.w, a[h]))));
            }
        ull b2[4] = {0ull,0ull,0ull,0ull};
#pragma unroll 4
        for (int c = 0; c < 128; c++) {
            float4 kc = *(const float4*)(kp_s + c*4);
            float rp = fmaxf(fmaf(rx,kc.x, fmaf(ry,kc.y, fmaf(rz,kc.z, kc.w))), 0.f);
            ull rr; PACKF(rr, rp, rp);
            const ull* qp = (const ull*)(qk_s + c*10);
            FFMA2(b2[0], rr, qp[0]);
            FFMA2(b2[1], rr, qp[1]);
            FFMA2(b2[2], rr, qp[2]);
            FFMA2(b2[3], rr, qp[3]);
        }
        float sc[8];
#pragma unroll
        for (int m = 0; m < 4; m++) {
            float blo, bhi; UNPKF(blo, bhi, b2[m]);
            sc[2*m]   = (a[2*m]   + blo) * 0.25f;
            sc[2*m+1] = (a[2*m+1] + bhi) * 0.25f;
        }
        if (ki < 0) {
#pragma unroll
            for (int h = 0; h < 8; h++) sc[h] = -3.0e38f;
        }

        // phase 3: softmax over keys (warp lanes), per head
        float attn[8];
#pragma unroll
        for (int h = 0; h < 8; h++) {
            float m = sc[h];
#pragma unroll
            for (int o = 16; o; o >>= 1) m = fmaxf(m, __shfl_xor_sync(0xffffffffu, m, o));
            float e = __expf(sc[h] - m);
            float s = e;
#pragma unroll
            for (int o = 16; o; o >>= 1) s += __shfl_xor_sync(0xffffffffu, s, o);
            attn[h] = e / s;
        }
#pragma unroll
        for (int m = 0; m < 4; m++) {
            ull p; PACKF(p, attn[2*m], attn[2*m+1]);
            *(ull*)(at_s + lane*10 + 2*m) = p;
        }
        __syncwarp();

        // phase 4a: att[c] = sum_k attn[h(c),k]*Vf[g_k][c];
        //           s[hh][c] = sum_k attn[hh,k]*relupos[k][c]
        ull sacc[4][4];
#pragma unroll
        for (int i = 0; i < 4; i++)
#pragma unroll
            for (int m = 0; m < 4; m++) sacc[i][m] = 0ull;
        float av[4] = {0.f, 0.f, 0.f, 0.f};
#pragma unroll 2
        for (int k = 0; k < 32; k++) {
            int   gk  = __shfl_sync(0xffffffffu, g,  k);
            float rkx = __shfl_sync(0xffffffffu, rx, k);
            float rky = __shfl_sync(0xffffffffu, ry, k);
            float rkz = __shfl_sync(0xffffffffu, rz, k);
            float4 v4 = *(const float4*)(KV + (size_t)gk*256 + 128 + cbase);
            const ull* a2 = (const ull*)(at_s + k*10);
            float ah = at_s[k*10 + hj];
#pragma unroll
            for (int i = 0; i < 4; i++) {
                float rp = fmaxf(fmaf(rkx,kp[i].x, fmaf(rky,kp[i].y,
                              fmaf(rkz,kp[i].z, kp[i].w))), 0.f);
                ull rr; PACKF(rr, rp, rp);
                FFMA2(sacc[i][0], rr, a2[0]);
                FFMA2(sacc[i][1], rr, a2[1]);
                FFMA2(sacc[i][2], rr, a2[2]);
                FFMA2(sacc[i][3], rr, a2[3]);
            }
            av[0] = fmaf(ah, v4.x, av[0]);
            av[1] = fmaf(ah, v4.y, av[1]);
            av[2] = fmaf(ah, v4.z, av[2]);
            av[3] = fmaf(ah, v4.w, av[3]);
        }
        __syncwarp();
#pragma unroll
        for (int i = 0; i < 4; i++)
#pragma unroll
            for (int m = 0; m < 4; m++)
                *(ull*)(qk_s + (cbase+i)*10 + 2*m) = sacc[i][m];
        __syncwarp();

        // phase 4b: att2[c] = att[c] + sum_c' s[h(c)][c'] * wv[c][c']
        ull o01 = 0ull, o23 = 0ull;
#pragma unroll 4
        for (int cp = 0; cp < 128; cp++) {
            float sv = qk_s[cp*10 + hj];
            ull ss; PACKF(ss, sv, sv);
            const ull* wp = (const ull*)(wv_s + cp*132 + cbase);
            FFMA2(o01, ss, wp[0]);
            FFMA2(o23, ss, wp[1]);
        }
        float o0,o1,o2,o3;
        UNPKF(o0,o1,o01); UNPKF(o2,o3,o23);
        *(float4*)(att2 + (size_t)nq*128 + cbase) =
            make_float4(av[0]+o0, av[1]+o1, av[2]+o2, av[3]+o3);
        __syncwarp();
    }
}

// ---- BN: deterministic two-stage stats ----
__global__ void bn_stats_kernel(const float* __restrict__ X, float* __restrict__ part, int n) {
    int c = threadIdx.x, r0 = blockIdx.x * 512;
    float s = 0.f, s2 = 0.f;
    for (int r = 0; r < 512; r++) {
        int row = r0 + r;
        if (row >= n) break;
        float v = X[(size_t)row*128 + c];
        s += v; s2 = fmaf(v, v, s2);
    }
    part[blockIdx.x*256 + c]       = s;
    part[blockIdx.x*256 + 128 + c] = s2;
}

__global__ void bn_reduce_kernel(const float* __restrict__ part, float* __restrict__ sums, int nb) {
    int c = threadIdx.x;
    float a = 0.f;
    for (int b = 0; b < nb; b++) a += part[b*256 + c];
    sums[c] = a;
}

__global__ void bn_apply_kernel(const float* __restrict__ X, const float* __restrict__ sums,
                                const float* __restrict__ g, const float* __restrict__ b,
                                float* __restrict__ Y, int n, int doRelu) {
    int idx = blockIdx.x * 256 + threadIdx.x;
    int c = idx & 127;
    if ((idx >> 7) >= n) return;
    float invn = 1.0f / (float)n;
    float mean = sums[c] * invn;
    float var  = sums[128 + c] * invn - mean * mean;
    float scl  = rsqrtf(var + EPSBN) * g[c];
    float v = (X[idx] - mean) * scl + b[c];
    Y[idx] = doRelu ? fmaxf(v, 0.f) : v;
}

// ---- host ----
static void launch_gemm(const float* X, const float* W, const float* b, float* Y,
                        const float* res, int relu, int n, int cin, int cout) {
    dim3 grid((n + 63) / 64, cout / 128);
    gemm_kernel<<<grid, 256, (64*128 + 128*129)*4>>>(X, W, b, Y, res, relu, n, cin, cout);
}

extern "C" void kernel_launch(void* const* d_in, const int* in_sizes, int n_in,
                              void* d_out, int out_size) {
    const float* features = (const float*)d_in[0];
    const int*   indices  = (const int*)  d_in[1];
    const int*   key_idx  = (const int*)  d_in[2];
    const float* ipw      = (const float*)d_in[3];
    const float* ipb      = (const float*)d_in[4];
    const float* out_w    = (const float*)d_in[5];
    const float* out_b    = (const float*)d_in[6];
    const float* qpos_w   = (const float*)d_in[7];
    const float* qpos_b   = (const float*)d_in[8];
    const float* kpos_w   = (const float*)d_in[9];
    const float* kpos_b   = (const float*)d_in[10];
    const float* n1g      = (const float*)d_in[11];
    const float* n1b      = (const float*)d_in[12];
    const float* n2g      = (const float*)d_in[13];
    const float* n2b      = (const float*)d_in[14];
    const float* l1w      = (const float*)d_in[15];
    const float* l1b      = (const float*)d_in[16];
    const float* l2w      = (const float*)d_in[17];
    const float* l2b      = (const float*)d_in[18];
    const float* ow       = (const float*)d_in[19];
    const float* ob       = (const float*)d_in[20];
    const float* bog      = (const float*)d_in[21];
    const float* bob      = (const float*)d_in[22];
    float* out = (float*)d_out;

    int n = in_sizes[0] / 128;

    float *coords,*q,*qh,*KV,*att2,*x1,*x1n,*ff1,*x2,*x2n,*y,*part,*sums;
    cudaGetSymbolAddress((void**)&coords, g_coords);
    cudaGetSymbolAddress((void**)&q,    g_q);
    cudaGetSymbolAddress((void**)&qh,   g_qh);
    cudaGetSymbolAddress((void**)&KV,   g_KV);
    cudaGetSymbolAddress((void**)&att2, g_att2);
    cudaGetSymbolAddress((void**)&x1,   g_x1);
    cudaGetSymbolAddress((void**)&x1n,  g_x1n);
    cudaGetSymbolAddress((void**)&ff1,  g_ff1);
    cudaGetSymbolAddress((void**)&x2,   g_x2);
    cudaGetSymbolAddress((void**)&x2n,  g_x2n);
    cudaGetSymbolAddress((void**)&y,    g_y);
    cudaGetSymbolAddress((void**)&part, g_part);
    cudaGetSymbolAddress((void**)&sums, g_sums);

    cudaFuncSetAttribute(gemm_kernel, cudaFuncAttributeMaxDynamicSharedMemorySize,
                         (64*128 + 128*129)*4);
    cudaFuncSetAttribute(attn_warp_kernel, cudaFuncAttributeMaxDynamicSharedMemorySize,
                         AT_SMEM_FLOATS*4);

    const float* wq  = ipw;
    const float* wk  = ipw + 128*128;
    const float* wv  = ipw + 2*128*128;
    const float* bq  = ipb;
    const float* bkv = ipb + 128;   // bk | bv contiguous

    int nb_pts = (n * 128 + 255) / 256;
    int nb_bn  = (n + 511) / 512;

    coords_q_kernel<<<nb_pts, 256>>>(indices, features, qpos_w, qpos_b, coords, q, n);

    launch_gemm(q,        wq, bq,  qh, nullptr, 0, n, 128, 128);
    launch_gemm(features, wk, bkv, KV, nullptr, 0, n, 128, 256);

    attn_warp_kernel<<<(n + AT_QPB - 1) / AT_QPB, 384, AT_SMEM_FLOATS*4>>>(
        key_idx, coords, qh, KV, wk, wv, kpos_w, kpos_b, att2, n);

    launch_gemm(att2, out_w, out_b, x1, features, 0, n, 128, 128);

    bn_stats_kernel<<<nb_bn, 128>>>(x1, part, n);
    bn_reduce_kernel<<<1, 256>>>(part, sums, nb_bn);
    bn_apply_kernel<<<nb_pts, 256>>>(x1, sums, n1g, n1b, x1n, n, 0);

    launch_gemm(x1n, l1w, l1b, ff1, nullptr, 1, n, 128, 512);
    launch_gemm(ff1, l2w, l2b, x2, x1n,     0, n, 512, 128);

    bn_stats_kernel<<<nb_bn, 128>>>(x2, part, n);
    bn_reduce_kernel<<<1, 256>>>(part, sums, nb_bn);
    bn_apply_kernel<<<nb_pts, 256>>>(x2, sums, n2g, n2b, x2n, n, 0);

    launch_gemm(x2n, ow, ob, y, nullptr, 0, n, 128, 128);

    bn_stats_kernel<<<nb_bn, 128>>>(y, part, n);
    bn_reduce_kernel<<<1, 256>>>(part, sums, nb_bn);
    bn_apply_kernel<<<nb_pts, 256>>>(y, sums, bog, bob, out, n, 1);
}

// round 15
// speedup vs baseline: 1.0013x; 1.0013x over previous
#include <cuda_runtime.h>
#include <math.h>
#include <stdint.h>

#define NPT 60000
#define EPSBN 1e-5f

typedef unsigned long long ull;

__device__ float g_coords[NPT * 3];
__device__ float g_q   [NPT * 128];
__device__ float g_qh  [NPT * 128];
__device__ float g_KV  [(size_t)NPT * 256];   // [n][Kf(128) | Vf(128)]
__device__ float g_att2[NPT * 128];
__device__ float g_x1  [NPT * 128];
__device__ float g_x1n [NPT * 128];
__device__ float g_ff1 [(size_t)NPT * 512];
__device__ float g_x2  [NPT * 128];
__device__ float g_x2n [NPT * 128];
__device__ float g_y   [NPT * 128];
__device__ float g_part[128 * 256];
__device__ float g_sums[256];

#define FFMA2(d, a, b) asm("fma.rn.f32x2 %0, %1, %2, %0;" : "+l"(d) : "l"(a), "l"(b))
#define PACKF(d, a, b) asm("mov.b64 %0, {%1, %2};" : "=l"(d) : "f"(a), "f"(b))
#define UNPKF(lo, hi, v) asm("mov.b64 {%0, %1}, %2;" : "=f"(lo), "=f"(hi) : "l"(v))

// ---- coords + q = features + relu(coords @ qpos_w.T + b) ----
__global__ void coords_q_kernel(const int* __restrict__ ind, const float* __restrict__ f,
                                const float* __restrict__ qpw, const float* __restrict__ qpb,
                                float* __restrict__ coords, float* __restrict__ q, int n) {
    int idx = blockIdx.x * 256 + threadIdx.x;
    int row = idx >> 7, c = idx & 127;
    if (row >= n) return;
    float cx = ((float)ind[row*4+3] + 0.5f) * 0.1f - 40.0f;
    float cy = ((float)ind[row*4+2] + 0.5f) * 0.1f - 40.0f;
    float cz = ((float)ind[row*4+1] + 0.5f) * 0.2f - 3.0f;
    if (c == 0) { coords[row*3+0]=cx; coords[row*3+1]=cy; coords[row*3+2]=cz; }
    float p = cx*qpw[c*3+0] + cy*qpw[c*3+1] + cz*qpw[c*3+2] + qpb[c];
    q[idx] = f[idx] + fmaxf(p, 0.0f);
}

// ---- GEMM (R7-proven scalar version): Y = [relu]( X @ W^T + bias [+ res] ) ----
__global__ void gemm_kernel(const float* __restrict__ X, const float* __restrict__ W,
                            const float* __restrict__ bias, float* __restrict__ Y,
                            const float* __restrict__ res, int doRelu,
                            int n, int cin, int cout) {
    extern __shared__ float sm[];
    float* Xs = sm;               // 64x128
    float* Ws = sm + 64 * 128;    // 128x129 transposed
    int row0 = blockIdx.x * 64, j0 = blockIdx.y * 128;
    int tid = threadIdx.x, tx = tid & 31, ty = tid >> 5;
    float acc[8][4];
#pragma unroll
    for (int r = 0; r < 8; r++) { acc[r][0]=acc[r][1]=acc[r][2]=acc[r][3]=0.f; }

    for (int c0 = 0; c0 < cin; c0 += 128) {
#pragma unroll
        for (int i = 0; i < 8; i++) {
            int l = tid + 256*i, r = l >> 5, c4 = l & 31;
            int row = row0 + r;
            float4 v = make_float4(0.f,0.f,0.f,0.f);
            if (row < n) v = *(const float4*)(X + (size_t)row*cin + c0 + (c4<<2));
            *(float4*)(Xs + r*128 + (c4<<2)) = v;
        }
#pragma unroll 8
        for (int i = 0; i < 64; i++) {
            int l = tid + 256*i, j = l >> 7, c = l & 127;
            Ws[c*129 + j] = W[(size_t)(j0+j)*cin + c0 + c];
        }
        __syncthreads();
#pragma unroll 2
        for (int c = 0; c < 128; ++c) {
            float w0 = Ws[c*129+tx],    w1 = Ws[c*129+tx+32];
            float w2 = Ws[c*129+tx+64], w3 = Ws[c*129+tx+96];
#pragma unroll
            for (int r = 0; r < 8; ++r) {
                float xv = Xs[(ty*8+r)*128 + c];
                acc[r][0]=fmaf(xv,w0,acc[r][0]); acc[r][1]=fmaf(xv,w1,acc[r][1]);
                acc[r][2]=fmaf(xv,w2,acc[r][2]); acc[r][3]=fmaf(xv,w3,acc[r][3]);
            }
        }
        __syncthreads();
    }
    float b0=bias[j0+tx], b1=bias[j0+tx+32], b2=bias[j0+tx+64], b3=bias[j0+tx+96];
#pragma unroll
    for (int r = 0; r < 8; ++r) {
        int row = row0 + ty*8 + r;
        if (row >= n) break;
        float v0=acc[r][0]+b0, v1=acc[r][1]+b1, v2=acc[r][2]+b2, v3=acc[r][3]+b3;
        size_t base = (size_t)row*cout + j0;
        if (res) { v0+=res[base+tx]; v1+=res[base+tx+32]; v2+=res[base+tx+64]; v3+=res[base+tx+96]; }
        if (doRelu) { v0=fmaxf(v0,0.f); v1=fmaxf(v1,0.f); v2=fmaxf(v2,0.f); v3=fmaxf(v3,0.f); }
        Y[base+tx]=v0; Y[base+tx+32]=v1; Y[base+tx+64]=v2; Y[base+tx+96]=v3;
    }
}

// ---- warp-per-query fused attention ----
// 384 threads = 12 warps; each warp handles 4 queries; lane = key (K=32).
// smem: wk[16384] | wvT[128*132] | kp[512] | per-warp{qh 128, qks 1280, attn 320}
#define AT_WARPS 12
#define AT_QPW 4
#define AT_QPB (AT_WARPS * AT_QPW)
#define AT_WARP_FLOATS (128 + 1280 + 320)
#define AT_SMEM_FLOATS (16384 + 128*132 + 512 + AT_WARPS*AT_WARP_FLOATS)

__global__ __launch_bounds__(384, 1) void attn_warp_kernel(
    const int* __restrict__ ki_g, const float* __restrict__ coords,
    const float* __restrict__ qh_g, const float* __restrict__ KV,
    const float* __restrict__ wk, const float* __restrict__ wv,
    const float* __restrict__ kpw, const float* __restrict__ kpb,
    float* __restrict__ att2, int n) {
    extern __shared__ float sm[];
    float* wk_s = sm;                        // [hd][c] 128x128
    float* wv_s = sm + 16384;                // [c'][c] pad 132
    float* kp_s = wv_s + 128*132;            // [c][4] = {w0,w1,w2,b}
    float* wbase = kp_s + 512;
    const int tid = threadIdx.x;
    const int w = tid >> 5, lane = tid & 31;
    float* qh_s = wbase + w * AT_WARP_FLOATS;    // 128
    float* qk_s = qh_s + 128;                    // [c][10] pairs (h)
    float* at_s = qk_s + 1280;                   // [k][10] pairs (h)

    for (int l = tid; l < 16384; l += 384) wk_s[l] = wk[l];
    for (int l = tid; l < 16384; l += 384) {
        int co = l >> 7, cp = l & 127;
        wv_s[cp*132 + co] = wv[l];
    }
    for (int c = tid; c < 128; c += 384) {
        kp_s[c*4+0] = kpw[c*3+0];
        kp_s[c*4+1] = kpw[c*3+1];
        kp_s[c*4+2] = kpw[c*3+2];
        kp_s[c*4+3] = kpb[c];
    }
    __syncthreads();

    const int cbase = lane << 2;       // this lane's 4 output channels
    const int hj    = lane >> 2;       // their head
    float4 kp[4];
#pragma unroll
    for (int i = 0; i < 4; i++) kp[i] = *(const float4*)(kp_s + (cbase+i)*4);

    for (int qi = 0; qi < AT_QPW; qi++) {
        int nq = blockIdx.x * AT_QPB + w * AT_QPW + qi;
        if (nq >= n) nq = n - 1;

        // phase 0: per-lane key meta + qh to smem
        int ki = ki_g[nq*32 + lane];
        int g  = ki < 0 ? 0 : ki;
        float qcx = coords[nq*3+0], qcy = coords[nq*3+1], qcz = coords[nq*3+2];
        float rx = coords[g*3+0] - qcx;
        float ry = coords[g*3+1] - qcy;
        float rz = coords[g*3+2] - qcz;
        *(float4*)(qh_s + cbase) = *(const float4*)(qh_g + (size_t)nq*128 + cbase);
        __syncwarp();

        // phase 1: qk[h][c] = sum_d qh[h*16+d]*wk[h*16+d][c], c in lane's 4 cols
        float acc[8][4];
#pragma unroll
        for (int h = 0; h < 8; h++) { acc[h][0]=acc[h][1]=acc[h][2]=acc[h][3]=0.f; }
#pragma unroll
        for (int h = 0; h < 8; h++)
#pragma unroll
            for (int d = 0; d < 16; d++) {
                float qv = qh_s[h*16+d];
                float4 w4 = *(const float4*)(wk_s + (h*16+d)*128 + cbase);
                acc[h][0]=fmaf(qv,w4.x,acc[h][0]); acc[h][1]=fmaf(qv,w4.y,acc[h][1]);
                acc[h][2]=fmaf(qv,w4.z,acc[h][2]); acc[h][3]=fmaf(qv,w4.w,acc[h][3]);
            }
#pragma unroll
        for (int i = 0; i < 4; i++)
#pragma unroll
            for (int m = 0; m < 4; m++) {
                ull p; PACKF(p, acc[2*m][i], acc[2*m+1][i]);
                *(ull*)(qk_s + (cbase+i)*10 + 2*m) = p;
            }
        __syncwarp();

        // phase 2: scores for this lane's key
        float a[8];
#pragma unroll
        for (int h = 0; h < 8; h++) a[h] = 0.f;
        const float4* kf4 = (const float4*)(KV + (size_t)g*256);
#pragma unroll
        for (int h = 0; h < 8; h++)
#pragma unroll
            for (int dq = 0; dq < 4; dq++) {
                float4 q4 = *(const float4*)(qh_s + h*16 + dq*4);
                float4 k4 = kf4[h*4 + dq];
                a[h] = fmaf(q4.x,k4.x, fmaf(q4.y,k4.y, fmaf(q4.z,k4.z,
                        fmaf(q4.w,k4.w, a[h]))));
            }
        ull b2[4] = {0ull,0ull,0ull,0ull};
#pragma unroll 4
        for (int c = 0; c < 128; c++) {
            float4 kc = *(const float4*)(kp_s + c*4);
            float rp = fmaxf(fmaf(rx,kc.x, fmaf(ry,kc.y, fmaf(rz,kc.z, kc.w))), 0.f);
            ull rr; PACKF(rr, rp, rp);
            const ull* qp = (const ull*)(qk_s + c*10);
            FFMA2(b2[0], rr, qp[0]);
            FFMA2(b2[1], rr, qp[1]);
            FFMA2(b2[2], rr, qp[2]);
            FFMA2(b2[3], rr, qp[3]);
        }
        float sc[8];
#pragma unroll
        for (int m = 0; m < 4; m++) {
            float blo, bhi; UNPKF(blo, bhi, b2[m]);
            sc[2*m]   = (a[2*m]   + blo) * 0.25f;
            sc[2*m+1] = (a[2*m+1] + bhi) * 0.25f;
        }
        if (ki < 0) {
#pragma unroll
            for (int h = 0; h < 8; h++) sc[h] = -3.0e38f;
        }

        // phase 3: softmax over keys (warp lanes), per head
        float attn[8];
#pragma unroll
        for (int h = 0; h < 8; h++) {
            float m = sc[h];
#pragma unroll
            for (int o = 16; o; o >>= 1) m = fmaxf(m, __shfl_xor_sync(0xffffffffu, m, o));
            float e = __expf(sc[h] - m);
            float s = e;
#pragma unroll
            for (int o = 16; o; o >>= 1) s += __shfl_xor_sync(0xffffffffu, s, o);
            attn[h] = e / s;
        }
#pragma unroll
        for (int m = 0; m < 4; m++) {
            ull p; PACKF(p, attn[2*m], attn[2*m+1]);
            *(ull*)(at_s + lane*10 + 2*m) = p;
        }
        __syncwarp();

        // phase 4a: att[c] = sum_k attn[h(c),k]*Vf[g_k][c];
        //           s[hh][c] = sum_k attn[hh,k]*relupos[k][c]
        ull sacc[4][4];
#pragma unroll
        for (int i = 0; i < 4; i++)
#pragma unroll
            for (int m = 0; m < 4; m++) sacc[i][m] = 0ull;
        float av[4] = {0.f, 0.f, 0.f, 0.f};
#pragma unroll 2
        for (int k = 0; k < 32; k++) {
            int   gk  = __shfl_sync(0xffffffffu, g,  k);
            float rkx = __shfl_sync(0xffffffffu, rx, k);
            float rky = __shfl_sync(0xffffffffu, ry, k);
            float rkz = __shfl_sync(0xffffffffu, rz, k);
            float4 v4 = *(const float4*)(KV + (size_t)gk*256 + 128 + cbase);
            const ull* a2 = (const ull*)(at_s + k*10);
            float ah = at_s[k*10 + hj];
#pragma unroll
            for (int i = 0; i < 4; i++) {
                float rp = fmaxf(fmaf(rkx,kp[i].x, fmaf(rky,kp[i].y,
                              fmaf(rkz,kp[i].z, kp[i].w))), 0.f);
                ull rr; PACKF(rr, rp, rp);
                FFMA2(sacc[i][0], rr, a2[0]);
                FFMA2(sacc[i][1], rr, a2[1]);
                FFMA2(sacc[i][2], rr, a2[2]);
                FFMA2(sacc[i][3], rr, a2[3]);
            }
            av[0] = fmaf(ah, v4.x, av[0]);
            av[1] = fmaf(ah, v4.y, av[1]);
            av[2] = fmaf(ah, v4.z, av[2]);
            av[3] = fmaf(ah, v4.w, av[3]);
        }
        __syncwarp();
#pragma unroll
        for (int i = 0; i < 4; i++)
#pragma unroll
            for (int m = 0; m < 4; m++)
                *(ull*)(qk_s + (cbase+i)*10 + 2*m) = sacc[i][m];
        __syncwarp();

        // phase 4b: att2[c] = att[c] + sum_c' s[h(c)][c'] * wv[c][c']
        ull o01 = 0ull, o23 = 0ull;
#pragma unroll 4
        for (int cp = 0; cp < 128; cp++) {
            float sv = qk_s[cp*10 + hj];
            ull ss; PACKF(ss, sv, sv);
            const ull* wp = (const ull*)(wv_s + cp*132 + cbase);
            FFMA2(o01, ss, wp[0]);
            FFMA2(o23, ss, wp[1]);
        }
        float o0,o1,o2,o3;
        UNPKF(o0,o1,o01); UNPKF(o2,o3,o23);
        *(float4*)(att2 + (size_t)nq*128 + cbase) =
            make_float4(av[0]+o0, av[1]+o1, av[2]+o2, av[3]+o3);
        __syncwarp();
    }
}

// ---- BN: deterministic two-stage stats ----
__global__ void bn_stats_kernel(const float* __restrict__ X, float* __restrict__ part, int n) {
    int c = threadIdx.x, r0 = blockIdx.x * 512;
    float s = 0.f, s2 = 0.f;
    for (int r = 0; r < 512; r++) {
        int row = r0 + r;
        if (row >= n) break;
        float v = X[(size_t)row*128 + c];
        s += v; s2 = fmaf(v, v, s2);
    }
    part[blockIdx.x*256 + c]       = s;
    part[blockIdx.x*256 + 128 + c] = s2;
}

__global__ void bn_reduce_kernel(const float* __restrict__ part, float* __restrict__ sums, int nb) {
    int c = threadIdx.x;
    float a = 0.f;
    for (int b = 0; b < nb; b++) a += part[b*256 + c];
    sums[c] = a;
}

__global__ void bn_apply_kernel(const float* __restrict__ X, const float* __restrict__ sums,
                                const float* __restrict__ g, const float* __restrict__ b,
                                float* __restrict__ Y, int n, int doRelu) {
    int idx = blockIdx.x * 256 + threadIdx.x;
    int c = idx & 127;
    if ((idx >> 7) >= n) return;
    float invn = 1.0f / (float)n;
    float mean = sums[c] * invn;
    float var  = sums[128 + c] * invn - mean * mean;
    float scl  = rsqrtf(var + EPSBN) * g[c];
    float v = (X[idx] - mean) * scl + b[c];
    Y[idx] = doRelu ? fmaxf(v, 0.f) : v;
}

// ---- host ----
static void launch_gemm(const float* X, const float* W, const float* b, float* Y,
                        const float* res, int relu, int n, int cin, int cout) {
    dim3 grid((n + 63) / 64, cout / 128);
    gemm_kernel<<<grid, 256, (64*128 + 128*129)*4>>>(X, W, b, Y, res, relu, n, cin, cout);
}

extern "C" void kernel_launch(void* const* d_in, const int* in_sizes, int n_in,
                              void* d_out, int out_size) {
    const float* features = (const float*)d_in[0];
    const int*   indices  = (const int*)  d_in[1];
    const int*   key_idx  = (const int*)  d_in[2];
    const float* ipw      = (const float*)d_in[3];
    const float* ipb      = (const float*)d_in[4];
    const float* out_w    = (const float*)d_in[5];
    const float* out_b    = (const float*)d_in[6];
    const float* qpos_w   = (const float*)d_in[7];
    const float* qpos_b   = (const float*)d_in[8];
    const float* kpos_w   = (const float*)d_in[9];
    const float* kpos_b   = (const float*)d_in[10];
    const float* n1g      = (const float*)d_in[11];
    const float* n1b      = (const float*)d_in[12];
    const float* n2g      = (const float*)d_in[13];
    const float* n2b      = (const float*)d_in[14];
    const float* l1w      = (const float*)d_in[15];
    const float* l1b      = (const float*)d_in[16];
    const float* l2w      = (const float*)d_in[17];
    const float* l2b      = (const float*)d_in[18];
    const float* ow       = (const float*)d_in[19];
    const float* ob       = (const float*)d_in[20];
    const float* bog      = (const float*)d_in[21];
    const float* bob      = (const float*)d_in[22];
    float* out = (float*)d_out;

    int n = in_sizes[0] / 128;

    float *coords,*q,*qh,*KV,*att2,*x1,*x1n,*ff1,*x2,*x2n,*y,*part,*sums;
    cudaGetSymbolAddress((void**)&coords, g_coords);
    cudaGetSymbolAddress((void**)&q,    g_q);
    cudaGetSymbolAddress((void**)&qh,   g_qh);
    cudaGetSymbolAddress((void**)&KV,   g_KV);
    cudaGetSymbolAddress((void**)&att2, g_att2);
    cudaGetSymbolAddress((void**)&x1,   g_x1);
    cudaGetSymbolAddress((void**)&x1n,  g_x1n);
    cudaGetSymbolAddress((void**)&ff1,  g_ff1);
    cudaGetSymbolAddress((void**)&x2,   g_x2);
    cudaGetSymbolAddress((void**)&x2n,  g_x2n);
    cudaGetSymbolAddress((void**)&y,    g_y);
    cudaGetSymbolAddress((void**)&part, g_part);
    cudaGetSymbolAddress((void**)&sums, g_sums);

    cudaFuncSetAttribute(gemm_kernel, cudaFuncAttributeMaxDynamicSharedMemorySize,
                         (64*128 + 128*129)*4);
    cudaFuncSetAttribute(attn_warp_kernel, cudaFuncAttributeMaxDynamicSharedMemorySize,
                         AT_SMEM_FLOATS*4);

    const float* wq  = ipw;
    const float* wk  = ipw + 128*128;
    const float* wv  = ipw + 2*128*128;
    const float* bq  = ipb;
    const float* bkv = ipb + 128;   // bk | bv contiguous

    int nb_pts = (n * 128 + 255) / 256;
    int nb_bn  = (n + 511) / 512;

    coords_q_kernel<<<nb_pts, 256>>>(indices, features, qpos_w, qpos_b, coords, q, n);

    launch_gemm(q,        wq, bq,  qh, nullptr, 0, n, 128, 128);
    launch_gemm(features, wk, bkv, KV, nullptr, 0, n, 128, 256);

    attn_warp_kernel<<<(n + AT_QPB - 1) / AT_QPB, 384, AT_SMEM_FLOATS*4>>>(
        key_idx, coords, qh, KV, wk, wv, kpos_w, kpos_b, att2, n);

    launch_gemm(att2, out_w, out_b, x1, features, 0, n, 128, 128);

    bn_stats_kernel<<<nb_bn, 128>>>(x1, part, n);
    bn_reduce_kernel<<<1, 256>>>(part, sums, nb_bn);
    bn_apply_kernel<<<nb_pts, 256>>>(x1, sums, n1g, n1b, x1n, n, 0);

    launch_gemm(x1n, l1w, l1b, ff1, nullptr, 1, n, 128, 512);
    launch_gemm(ff1, l2w, l2b, x2, x1n,     0, n, 512, 128);

    bn_stats_kernel<<<nb_bn, 128>>>(x2, part, n);
    bn_reduce_kernel<<<1, 256>>>(part, sums, nb_bn);
    bn_apply_kernel<<<nb_pts, 256>>>(x2, sums, n2g, n2b, x2n, n, 0);

    launch_gemm(x2n, ow, ob, y, nullptr, 0, n, 128, 128);

    bn_stats_kernel<<<nb_bn, 128>>>(y, part, n);
    bn_reduce_kernel<<<1, 256>>>(part, sums, nb_bn);
    bn_apply_kernel<<<nb_pts, 256>>>(y, sums, bog, bob, out, n, 1);
}